// round 14
// baseline (speedup 1.0000x reference)
#include <cuda_runtime.h>

#define NSYMB  50000
#define NMODES 2
#define LEAD   20000               // pilot prefix length (mask == (k >= LEAD))

#define L_SEG  20                  // output symbols per segment
#define S_SEG  2500                // segments per mode
#define W_UP   32                  // warm-up steps
#define T_TOT  52                  // W_UP + L_SEG
#define SEGB   16                  // segments per block
#define NBLK   ((S_SEG + SEGB - 1) / SEGB)   // 157 blocks
#define EWIN   96                  // est window (two 48-halves, 24 chunks of 4)

// Block symbol range: pll needs kbase..kbase+351, est ..kbase+395 -> 400.
#define NRANGE_SYM 400
#define NELEM  (NRANGE_SYM * 2)    // 800 interleaved elements
#define NVEC   (NELEM / 4)         // 200 float4 groups (4-aligned boundaries)
#define PHYS   912                 // NELEM + NELEM/8 padding, rounded
#define NCHK   100                 // chunk-of-4 sums per mode
#define CPITCH 104                 // padded chunk row pitch

__global__ void __launch_bounds__(128, 1) fused_kernel(
    const float* __restrict__ Ei_re, const float* __restrict__ Ei_im,
    const float* __restrict__ tx_re, const float* __restrict__ tx_im,
    const float* __restrict__ eta_n, const float* __restrict__ eta_f,
    float2*      __restrict__ out)
{
    __shared__ float  smYr[PHYS], smYi[PHYS], smXr[PHYS], smXi[PHYS];
    __shared__ float2 smC[2 * CPITCH];      // chunk sums of z = y*conj(x)

    const int tid = threadIdx.x;
    const int s0  = blockIdx.x * SEGB;
    const int kbase = s0 * L_SEG - W_UP;
    const int vbase = (kbase * 2) / 4;      // exact: kbase*2 = 640*blk - 64

    // ---- phase 1: vectorized coalesced fill (OOB -> zeros = PLL no-op) ----
    #pragma unroll
    for (int ii = 0; ii < (NVEC + 127) / 128; ++ii) {
        const int v = ii * 128 + tid;
        if (v < NVEC) {
            const int gv = vbase + v;
            float4 vyr = make_float4(0.f, 0.f, 0.f, 0.f), vyi = vyr;
            float4 vxr = vyr, vxi = vyr;
            if (gv >= 0 && gv < (2 * NSYMB) / 4) {
                vyr = ((const float4*)Ei_re)[gv];
                vyi = ((const float4*)Ei_im)[gv];
                vxr = ((const float4*)tx_re)[gv];
                vxi = ((const float4*)tx_im)[gv];
            }
            const int i0 = v * 4;
            #pragma unroll
            for (int u = 0; u < 4; ++u) {
                const int p = (i0 + u) + ((i0 + u) >> 3);
                smYr[p] = ((const float*)&vyr)[u];
                smYi[p] = ((const float*)&vyi)[u];
                smXr[p] = ((const float*)&vxr)[u];
                smXi[p] = ((const float*)&vxi)[u];
            }
        }
    }
    __syncthreads();

    // ---- phase 2: chunk sums (100 chunks x 2 modes, 4 symbols each) ----
    #pragma unroll
    for (int jj = 0; jj < 2; ++jj) {
        const int job = jj * 128 + tid;
        if (job < 2 * NCHK) {
            const int c = job >> 1, mm = job & 1;
            float sr = 0.f, si = 0.f;
            #pragma unroll
            for (int u = 0; u < 4; ++u) {
                const int i = (c * 4 + u) * 2 + mm;
                const int p = i + (i >> 3);
                const float yr = smYr[p], yi = smYi[p];
                const float xr = smXr[p], xi = smXi[p];
                sr = fmaf(yr, xr, fmaf(yi, xi, sr));
                si = fmaf(yi, xr, fmaf(-yr, xi, si));
            }
            smC[mm * CPITCH + c] = make_float2(sr, si);
        }
    }
    __syncthreads();

    if (tid >= 2 * SEGB) return;
    const int sl = tid >> 1;
    const int m  = tid & 1;
    const int s  = s0 + sl;
    if (s >= S_SEG) return;
    const int k0 = s * L_SEG - W_UP;     // negative for s=0,1

    const float Kn   = tanhf(eta_n[0]);
    const float Kf   = tanhf(eta_f[0]);
    const float Ksum = Kn + Kf;

    const float C1 = 0.316227766016837933f;  // 1/sqrt(10)
    const float C3 = 0.948683298050513800f;  // 3/sqrt(10)
    const float T2 = 0.632455532033675866f;  // 2/sqrt(10)

    // ---- phase 3: warm start from chunk sums (no transcendentals) ----
    float pc = 1.f, ps = 0.f, w = 0.f;
    if (k0 > 0) {
        int start = k0;
        if (start > NSYMB - EWIN) start = NSYMB - EWIN;   // both 4-aligned
        const int c0 = (start - kbase) >> 2;

        float Ar = 0.f, Ai = 0.f, Br = 0.f, Bi = 0.f;
        #pragma unroll
        for (int j = 0; j < 12; ++j) {
            const float2 za = smC[m * CPITCH + c0 + j];
            const float2 zb = smC[m * CPITCH + c0 + 12 + j];
            Ar += za.x; Ai += za.y;
            Br += zb.x; Bi += zb.y;
        }
        // q = B*conj(A): angle(q) = 48*w (small)
        const float qr = fmaf(Br, Ar,  Bi * Ai);
        const float qi = fmaf(Bi, Ar, -Br * Ai);
        const float z  = __fdividef(qi, qr);
        const float z2 = z * z;
        const float d  = z * fmaf(z2, fmaf(z2, 0.2f, -0.333333333f), 1.f); // atan
        w = d * (1.0f / 48.0f);
        // phi(k0) = angle(A) + offs*w ; p0 = unit(A) * e^{i*offs*w}
        const float offs = (float)(k0 - start) - 23.5f;
        const float a  = offs * w;
        const float a2 = a * a;
        const float ca = fmaf(a2, fmaf(a2, 4.16666667e-2f, -0.5f), 1.f);
        const float sa = a * fmaf(a2, -0.166666667f, 1.f);
        const float rn = rsqrtf(fmaf(Ar, Ar, Ai * Ai));
        const float pAr = Ar * rn, pAi = Ai * rn;
        pc = fmaf(pAr, ca, -pAi * sa);
        ps = fmaf(pAi, ca,  pAr * sa);
    }

    // ---- phase 4: 52-step PLL chain; writes final rotated output ----
    const int base_i = sl * (L_SEG * 2) + m;
    #pragma unroll 4
    for (int t = 0; t < T_TOT; ++t) {
        const int k = k0 + t;
        const int i = base_i + 2 * t;
        const int p = i + (i >> 3);
        const float yr = smYr[p], yi = smYi[p];

        // shared products: de-rotation (chain) and output (off-chain)
        const float yrpc = yr * pc, yips = yi * ps;
        const float yipc = yi * pc, yrps = yr * ps;
        const float rr = yrpc + yips;     // Re(y e^{-i theta})
        const float ri = yipc - yrps;     // Im(y e^{-i theta})

        if (t >= W_UP)                    // Eo = Ei * e^{i theta}
            out[k * NMODES + m] = make_float2(yrpc - yips, yrps + yipc);

        float cr, ci;
        if (k >= LEAD) {                  // decision-directed (mask structural)
            cr = copysignf((fabsf(rr) > T2) ? C3 : C1, rr);
            ci = copysignf((fabsf(ri) > T2) ? C3 : C1, ri);
        } else {                          // pilot (x=0 in padding -> g=0 no-op)
            cr = smXr[p]; ci = smXi[p];
        }

        const float gk  = 2.f * fmaf(rr, ci, -ri * cr);
        const float dlt = fmaf(-Ksum, gk, w);
        w = fmaf(-Kf, gk, w);

        // e^{i dlt} via short Taylor (|dlt| small after warm start)
        const float x2 = dlt * dlt;
        const float sp = fmaf(x2, fmaf(x2, 8.33333333e-3f, -0.166666667f), 1.0f);
        const float sd = dlt * sp;
        const float cd = fmaf(x2, fmaf(x2, fmaf(x2, -1.38888889e-3f,
                                 4.16666667e-2f), -0.5f), 1.0f);
        const float npc = fmaf(-ps, sd, pc * cd);
        const float nps = fmaf( pc, sd, ps * cd);
        pc = npc; ps = nps;

        if ((t & 7) == 7) {               // Newton renorm every 8 steps
            const float n2 = fmaf(pc, pc, ps * ps);
            const float h  = fmaf(-0.5f, n2, 1.5f);
            pc *= h; ps *= h;
        }
    }
}

extern "C" void kernel_launch(void* const* d_in, const int* in_sizes, int n_in,
                              void* d_out, int out_size)
{
    const float* Ei_re = (const float*)d_in[0];
    const float* Ei_im = (const float*)d_in[1];
    const float* tx_re = (const float*)d_in[2];
    const float* tx_im = (const float*)d_in[3];
    const float* eta_n = (const float*)d_in[4];
    const float* eta_f = (const float*)d_in[5];
    float2* out = (float2*)d_out;

    fused_kernel<<<NBLK, 128>>>(Ei_re, Ei_im, tx_re, tx_im, eta_n, eta_f, out);
}

// round 16
// speedup vs baseline: 1.0934x; 1.0934x over previous
#include <cuda_runtime.h>

#define NSYMB  50000
#define NMODES 2
#define LEAD   20000               // pilot prefix length (mask == (k >= LEAD))

#define L_SEG  20                  // output symbols per segment
#define S_SEG  2500                // segments per mode
#define W_UP   28                  // warm-up steps
#define T_TOT  48                  // W_UP + L_SEG
#define SEGB   20                  // segments per block
#define NBLK   (S_SEG / SEGB)      // 125 blocks -> one wave on 148 SMs
#define EWIN   96                  // est window (two 48-halves, 24 chunks of 4)

// Block symbol range: pll needs kbase..kbase+427, est ..kbase+475 -> 480.
#define NRANGE_SYM 480
#define NELEM  (NRANGE_SYM * 2)    // 960 interleaved elements
#define NVEC   (NELEM / 4)         // 240 float4 groups (4-aligned boundaries)
#define PHYS   1088                // NELEM + NELEM/8 padding, rounded
#define NCHK   120                 // chunk-of-4 sums per mode
#define CPITCH 128                 // padded chunk row pitch

__global__ void __launch_bounds__(128, 1) fused_kernel(
    const float* __restrict__ Ei_re, const float* __restrict__ Ei_im,
    const float* __restrict__ tx_re, const float* __restrict__ tx_im,
    const float* __restrict__ eta_n, const float* __restrict__ eta_f,
    float2*      __restrict__ out)
{
    __shared__ float  smYr[PHYS], smYi[PHYS], smXr[PHYS], smXi[PHYS];
    __shared__ float2 smC[2 * CPITCH];      // chunk sums of z = y*conj(x)

    const int tid = threadIdx.x;
    const int s0  = blockIdx.x * SEGB;
    const int kbase = s0 * L_SEG - W_UP;
    const int vbase = (kbase * 2) / 4;      // exact: kbase*2 = 800*blk - 56

    // ---- phase 1: vectorized coalesced fill (OOB -> zeros = PLL no-op) ----
    #pragma unroll
    for (int ii = 0; ii < (NVEC + 127) / 128; ++ii) {
        const int v = ii * 128 + tid;
        if (v < NVEC) {
            const int gv = vbase + v;
            float4 vyr = make_float4(0.f, 0.f, 0.f, 0.f), vyi = vyr;
            float4 vxr = vyr, vxi = vyr;
            if (gv >= 0 && gv < (2 * NSYMB) / 4) {
                vyr = ((const float4*)Ei_re)[gv];
                vyi = ((const float4*)Ei_im)[gv];
                vxr = ((const float4*)tx_re)[gv];
                vxi = ((const float4*)tx_im)[gv];
            }
            const int i0 = v * 4;
            #pragma unroll
            for (int u = 0; u < 4; ++u) {
                const int p = (i0 + u) + ((i0 + u) >> 3);
                smYr[p] = ((const float*)&vyr)[u];
                smYi[p] = ((const float*)&vyi)[u];
                smXr[p] = ((const float*)&vxr)[u];
                smXi[p] = ((const float*)&vxi)[u];
            }
        }
    }
    __syncthreads();

    // ---- phase 2: chunk sums (120 chunks x 2 modes, 4 symbols each) ----
    #pragma unroll
    for (int jj = 0; jj < 2; ++jj) {
        const int job = jj * 128 + tid;
        if (job < 2 * NCHK) {
            const int c = job >> 1, mm = job & 1;
            float sr = 0.f, si = 0.f;
            #pragma unroll
            for (int u = 0; u < 4; ++u) {
                const int i = (c * 4 + u) * 2 + mm;
                const int p = i + (i >> 3);
                const float yr = smYr[p], yi = smYi[p];
                const float xr = smXr[p], xi = smXi[p];
                sr = fmaf(yr, xr, fmaf(yi, xi, sr));
                si = fmaf(yi, xr, fmaf(-yr, xi, si));
            }
            smC[mm * CPITCH + c] = make_float2(sr, si);
        }
    }
    __syncthreads();

    if (tid >= 2 * SEGB) return;
    const int sl = tid >> 1;
    const int m  = tid & 1;
    const int k0 = (s0 + sl) * L_SEG - W_UP;   // negative for s=0

    const float Kn  = tanhf(eta_n[0]);
    const float Kf  = tanhf(eta_f[0]);
    const float K2s = 2.f * (Kn + Kf);
    const float K2f = 2.f * Kf;

    const float C1 = 0.316227766016837933f;  // 1/sqrt(10)
    const float C3 = 0.948683298050513800f;  // 3/sqrt(10)
    const float T2 = 0.632455532033675866f;  // 2/sqrt(10)

    // ---- phase 3: warm start from chunk sums (no transcendentals) ----
    float pc = 1.f, ps = 0.f, w = 0.f;
    if (k0 > 0) {
        int start = k0;
        if (start > NSYMB - EWIN) start = NSYMB - EWIN;   // both 4-aligned
        const int c0 = (start - kbase) >> 2;

        float Ar = 0.f, Ai = 0.f, Br = 0.f, Bi = 0.f;
        #pragma unroll
        for (int j = 0; j < 12; ++j) {
            const float2 za = smC[m * CPITCH + c0 + j];
            const float2 zb = smC[m * CPITCH + c0 + 12 + j];
            Ar += za.x; Ai += za.y;
            Br += zb.x; Bi += zb.y;
        }
        // q = B*conj(A): angle(q) = 48*w (small)
        const float qr = fmaf(Br, Ar,  Bi * Ai);
        const float qi = fmaf(Bi, Ar, -Br * Ai);
        const float z  = __fdividef(qi, qr);
        const float z2 = z * z;
        const float d  = z * fmaf(z2, fmaf(z2, 0.2f, -0.333333333f), 1.f); // atan
        w = d * (1.0f / 48.0f);
        // phi(k0) = angle(A) + offs*w ; p0 = unit(A) * e^{i*offs*w}
        const float offs = (float)(k0 - start) - 23.5f;
        const float a  = offs * w;
        const float a2 = a * a;
        const float ca = fmaf(a2, fmaf(a2, 4.16666667e-2f, -0.5f), 1.f);
        const float sa = a * fmaf(a2, -0.166666667f, 1.f);
        const float rn = rsqrtf(fmaf(Ar, Ar, Ai * Ai));
        const float pAr = Ar * rn, pAi = Ai * rn;
        pc = fmaf(pAr, ca, -pAi * sa);
        ps = fmaf(pAi, ca,  pAr * sa);
    }

    // ---- phase 4: 48-step PLL chain; writes final rotated output ----
    const int base_i = sl * (L_SEG * 2) + m;
    #pragma unroll 4
    for (int t = 0; t < T_TOT; ++t) {
        const int k = k0 + t;
        const int i = base_i + 2 * t;
        const int p = i + (i >> 3);
        const float yr = smYr[p], yi = smYi[p];

        // shared products: de-rotation (chain) and output (off-chain)
        const float yrpc = yr * pc, yips = yi * ps;
        const float yipc = yi * pc, yrps = yr * ps;
        const float rr = yrpc + yips;     // Re(y e^{-i theta})
        const float ri = yipc - yrps;     // Im(y e^{-i theta})

        if (t >= W_UP)                    // Eo = Ei * e^{i theta}
            out[k * NMODES + m] = make_float2(yrpc - yips, yrps + yipc);

        float cr, ci;
        if (k >= LEAD) {                  // decision-directed (mask structural)
            cr = copysignf((fabsf(rr) > T2) ? C3 : C1, rr);
            ci = copysignf((fabsf(ri) > T2) ? C3 : C1, ri);
        } else {                          // pilot (x=0 in padding -> g=0 no-op)
            cr = smXr[p]; ci = smXi[p];
        }

        // gk' = g/2; the 2x is folded into K2s/K2f
        const float gk  = fmaf(rr, ci, -ri * cr);
        const float dlt = fmaf(-K2s, gk, w);
        w = fmaf(-K2f, gk, w);

        // e^{i dlt}: short Taylor (|dlt| small after warm start)
        const float x2 = dlt * dlt;
        const float sd = dlt * fmaf(x2, -0.166666667f, 1.0f);
        const float cd = fmaf(x2, fmaf(x2, 4.16666667e-2f, -0.5f), 1.0f);
        const float npc = fmaf(-ps, sd, pc * cd);
        const float nps = fmaf( pc, sd, ps * cd);
        pc = npc; ps = nps;

        if ((t & 7) == 7) {               // Newton renorm every 8 steps
            const float n2 = fmaf(pc, pc, ps * ps);
            const float h  = fmaf(-0.5f, n2, 1.5f);
            pc *= h; ps *= h;
        }
    }
}

extern "C" void kernel_launch(void* const* d_in, const int* in_sizes, int n_in,
                              void* d_out, int out_size)
{
    const float* Ei_re = (const float*)d_in[0];
    const float* Ei_im = (const float*)d_in[1];
    const float* tx_re = (const float*)d_in[2];
    const float* tx_im = (const float*)d_in[3];
    const float* eta_n = (const float*)d_in[4];
    const float* eta_f = (const float*)d_in[5];
    float2* out = (float2*)d_out;

    fused_kernel<<<NBLK, 128>>>(Ei_re, Ei_im, tx_re, tx_im, eta_n, eta_f, out);
}